// round 7
// baseline (speedup 1.0000x reference)
#include <cuda_runtime.h>
#include <cstdint>

// out[b, t, h] = sum_{j=0..4} x[b, t+j, h] * a[b, t+j]
// x: (32,1,2052,768) f32, a: (32,2052) f32, out: (32,1,2048,768) f32
//
// R7: bulk-DMA input pipeline + register sliding window + DIRECT STG output.
//   - No output smem ring: each thread computes 4 output rows in registers
//     and stores them with STG.128 (streaming). Halves smem-port traffic and
//     removes store-drain serialization from the per-chunk critical path.
//   - 6-stage (72KB) input ring; one __syncthreads + one mbar-wait per chunk.

constexpr int LENGTH = 2048;
constexpr int H      = 768;
constexpr int PAD    = LENGTH + 4;           // 2052
constexpr int ROWB   = H * 4;                // 3072 B per row
constexpr int H4     = H / 4;                // 192
constexpr int NSEG   = 9;                    // segments per batch row
constexpr int SEGR   = 228;                  // rows per segment (last = 224)
constexpr int CR     = 4;                    // rows per chunk
constexpr int CHUNK  = CR * ROWB;            // 12288 B
constexpr int IN_STAGES = 6;
constexpr int B      = 32;
constexpr int THREADS = H4;                  // 192

constexpr int MBAR_OFF = 0;                              // 6 mbarriers * 8B
constexpr int WA_OFF   = 64;                             // 232 floats
constexpr int IN_OFF   = 1024;
constexpr int SMEM_TOTAL = IN_OFF + IN_STAGES * CHUNK;   // 74752 B

__device__ __forceinline__ uint32_t smem_u32(const void* p) {
    return (uint32_t)__cvta_generic_to_shared(p);
}
__device__ __forceinline__ void mbar_init(uint32_t bar, uint32_t count) {
    asm volatile("mbarrier.init.shared.b64 [%0], %1;" :: "r"(bar), "r"(count) : "memory");
}
__device__ __forceinline__ void mbar_expect_tx(uint32_t bar, uint32_t bytes) {
    asm volatile("mbarrier.arrive.expect_tx.shared.b64 _, [%0], %1;"
                 :: "r"(bar), "r"(bytes) : "memory");
}
__device__ __forceinline__ void mbar_wait(uint32_t bar, uint32_t parity) {
    uint32_t done;
    asm volatile(
        "{\n\t.reg .pred p;\n\t"
        "mbarrier.try_wait.parity.acquire.cta.shared::cta.b64 p, [%1], %2;\n\t"
        "selp.b32 %0, 1, 0, p;\n\t}"
        : "=r"(done) : "r"(bar), "r"(parity) : "memory");
    if (!done) {
        asm volatile(
            "{\n\t.reg .pred P1;\n\t"
            "W_%=:\n\t"
            "mbarrier.try_wait.parity.acquire.cta.shared::cta.b64 P1, [%0], %1, 0x989680;\n\t"
            "@P1 bra.uni D_%=;\n\t"
            "bra.uni W_%=;\n\t"
            "D_%=:\n\t}"
            :: "r"(bar), "r"(parity) : "memory");
    }
}
__device__ __forceinline__ void bulk_g2s(uint32_t dst_smem, const void* src_gmem,
                                         uint32_t bytes, uint32_t bar) {
    asm volatile(
        "cp.async.bulk.shared::cluster.global.mbarrier::complete_tx::bytes "
        "[%0], [%1], %2, [%3];"
        :: "r"(dst_smem), "l"(src_gmem), "r"(bytes), "r"(bar) : "memory");
}

__global__ __launch_bounds__(THREADS, 3) void widthap_kernel(
    const float* __restrict__ x,
    const float* __restrict__ att,
    float* __restrict__ out)
{
    extern __shared__ char smem[];
    const int tid = threadIdx.x;     // 0..191 = float4 column
    const int b   = blockIdx.y;
    const int seg = blockIdx.x;
    const int t0  = seg * SEGR;
    const int rows = (seg == NSEG - 1) ? (LENGTH - t0) : SEGR;  // 228 or 224
    const int NCH  = rows / CR;                                  // 57 or 56
    const int NIN  = NCH + 1;

    uint32_t sbase = smem_u32(smem);
    uint32_t mbar  = sbase + MBAR_OFF;

    float* wa = reinterpret_cast<float*>(smem + WA_OFF);
    for (int i = tid; i < rows + 4; i += THREADS)
        wa[i] = att[b * PAD + t0 + i];

    if (tid == 0) {
        #pragma unroll
        for (int s = 0; s < IN_STAGES; s++)
            mbar_init(mbar + s * 8, 1);
    }
    __syncthreads();

    const char* xsrc = reinterpret_cast<const char*>(x) +
                       ((size_t)b * PAD + t0) * ROWB;
    float4* ob = reinterpret_cast<float4*>(out + (size_t)b * LENGTH * H +
                                           (size_t)t0 * H) + tid;

    // prime input chunks 0..5
    if (tid == 0) {
        #pragma unroll
        for (int ci = 0; ci < IN_STAGES; ci++) {
            mbar_expect_tx(mbar + ci * 8, CHUNK);
            bulk_g2s(sbase + IN_OFF + ci * CHUNK,
                     xsrc + (size_t)ci * CHUNK, CHUNK, mbar + ci * 8);
        }
    }

    // Prologue: consume chunk 0 into register window (rows 0..3, weighted)
    float4 w0, w1, w2, w3;
    {
        mbar_wait(mbar + 0, 0);
        const float4* in0 = reinterpret_cast<const float4*>(smem + IN_OFF);
        float4 v;
        v = in0[0 * H4 + tid]; w0 = make_float4(v.x*wa[0], v.y*wa[0], v.z*wa[0], v.w*wa[0]);
        v = in0[1 * H4 + tid]; w1 = make_float4(v.x*wa[1], v.y*wa[1], v.z*wa[1], v.w*wa[1]);
        v = in0[2 * H4 + tid]; w2 = make_float4(v.x*wa[2], v.y*wa[2], v.z*wa[2], v.w*wa[2]);
        v = in0[3 * H4 + tid]; w3 = make_float4(v.x*wa[3], v.y*wa[3], v.z*wa[3], v.w*wa[3]);
    }

    for (int co = 0; co < NCH; co++) {
        // Barrier: all reads of chunk co (done last iteration, or prologue)
        // have retired -> its stage (co % 6) may be refilled.
        __syncthreads();

        if (tid == 0) {
            int ci = co + IN_STAGES;           // lands in stage co % 6
            if (ci < NIN) {
                int s = ci % IN_STAGES;
                mbar_expect_tx(mbar + s * 8, CHUNK);
                bulk_g2s(sbase + IN_OFF + s * CHUNK,
                         xsrc + (size_t)ci * CHUNK, CHUNK, mbar + s * 8);
            }
        }

        // Consume input chunk co+1 (each smem byte read exactly once)
        const int ci = co + 1;
        mbar_wait(mbar + (ci % IN_STAGES) * 8, (ci / IN_STAGES) & 1);

        const float4* in = reinterpret_cast<const float4*>(
            smem + IN_OFF + (ci % IN_STAGES) * CHUNK);
        const int wb = 4 * co + 4;
        float4 n0, n1, n2, n3, v;
        v = in[0 * H4 + tid]; { float a = wa[wb+0]; n0 = make_float4(v.x*a, v.y*a, v.z*a, v.w*a); }
        v = in[1 * H4 + tid]; { float a = wa[wb+1]; n1 = make_float4(v.x*a, v.y*a, v.z*a, v.w*a); }
        v = in[2 * H4 + tid]; { float a = wa[wb+2]; n2 = make_float4(v.x*a, v.y*a, v.z*a, v.w*a); }
        v = in[3 * H4 + tid]; { float a = wa[wb+3]; n3 = make_float4(v.x*a, v.y*a, v.z*a, v.w*a); }

        // Direct streaming stores of the 4 output rows
        float4* orow = ob + (size_t)(4 * co) * H4;
        float4 s;
        s.x = w0.x+w1.x+w2.x+w3.x+n0.x; s.y = w0.y+w1.y+w2.y+w3.y+n0.y;
        s.z = w0.z+w1.z+w2.z+w3.z+n0.z; s.w = w0.w+w1.w+w2.w+w3.w+n0.w;
        __stcs(orow + 0 * H4, s);
        s.x = w1.x+w2.x+w3.x+n0.x+n1.x; s.y = w1.y+w2.y+w3.y+n0.y+n1.y;
        s.z = w1.z+w2.z+w3.z+n0.z+n1.z; s.w = w1.w+w2.w+w3.w+n0.w+n1.w;
        __stcs(orow + 1 * H4, s);
        s.x = w2.x+w3.x+n0.x+n1.x+n2.x; s.y = w2.y+w3.y+n0.y+n1.y+n2.y;
        s.z = w2.z+w3.z+n0.z+n1.z+n2.z; s.w = w2.w+w3.w+n0.w+n1.w+n2.w;
        __stcs(orow + 2 * H4, s);
        s.x = w3.x+n0.x+n1.x+n2.x+n3.x; s.y = w3.y+n0.y+n1.y+n2.y+n3.y;
        s.z = w3.z+n0.z+n1.z+n2.z+n3.z; s.w = w3.w+n0.w+n1.w+n2.w+n3.w;
        __stcs(orow + 3 * H4, s);

        w0 = n0; w1 = n1; w2 = n2; w3 = n3;
    }
}

extern "C" void kernel_launch(void* const* d_in, const int* in_sizes, int n_in,
                              void* d_out, int out_size)
{
    const float* x   = (const float*)d_in[0];   // (32,1,2052,768)
    const float* att = (const float*)d_in[1];   // (32,2052)
    float* out       = (float*)d_out;           // (32,1,2048,768)

    cudaFuncSetAttribute(widthap_kernel,
                         cudaFuncAttributeMaxDynamicSharedMemorySize, SMEM_TOTAL);

    dim3 grid(NSEG, B);   // (9, 32) = 288 CTAs
    dim3 block(THREADS);  // 192
    widthap_kernel<<<grid, block, SMEM_TOTAL>>>(x, att, out);
}

// round 8
// speedup vs baseline: 1.0130x; 1.0130x over previous
#include <cuda_runtime.h>
#include <cstdint>

// out[b, t, h] = sum_{j=0..4} x[b, t+j, h] * a[b, t+j]
// x: (32,1,2052,768) f32, a: (32,2052) f32, out: (32,1,2048,768) f32
//
// R8: R5's bulk-DMA in/out pipeline + register sliding window, resized for
//     3 CTAs/SM: 4-stage input ring + 2-stage output ring = 74.75KB smem.
//     Grid = 13 segments x 32 batches = 416 CTAs (<=444 resident) => 1 wave.

constexpr int LENGTH = 2048;
constexpr int H      = 768;
constexpr int PAD    = LENGTH + 4;           // 2052
constexpr int ROWB   = H * 4;                // 3072 B per row
constexpr int H4     = H / 4;                // 192
constexpr int NSEG   = 13;
constexpr int SEGR   = 160;                  // rows/segment (last = 128)
constexpr int CR     = 4;                    // rows per chunk
constexpr int CHUNK  = CR * ROWB;            // 12288 B
constexpr int IN_STAGES  = 4;
constexpr int OUT_STAGES = 2;
constexpr int B      = 32;
constexpr int THREADS = H4;                  // 192

constexpr int MBAR_OFF = 0;                              // 4 mbarriers * 8B
constexpr int WA_OFF   = 64;                             // up to 164 floats
constexpr int IN_OFF   = 1024;
constexpr int OUT_OFF  = IN_OFF + IN_STAGES * CHUNK;     // 50176
constexpr int SMEM_TOTAL = OUT_OFF + OUT_STAGES * CHUNK; // 74752

__device__ __forceinline__ uint32_t smem_u32(const void* p) {
    return (uint32_t)__cvta_generic_to_shared(p);
}
__device__ __forceinline__ void mbar_init(uint32_t bar, uint32_t count) {
    asm volatile("mbarrier.init.shared.b64 [%0], %1;" :: "r"(bar), "r"(count) : "memory");
}
__device__ __forceinline__ void mbar_expect_tx(uint32_t bar, uint32_t bytes) {
    asm volatile("mbarrier.arrive.expect_tx.shared.b64 _, [%0], %1;"
                 :: "r"(bar), "r"(bytes) : "memory");
}
__device__ __forceinline__ void mbar_wait(uint32_t bar, uint32_t parity) {
    uint32_t done;
    asm volatile(
        "{\n\t.reg .pred p;\n\t"
        "mbarrier.try_wait.parity.acquire.cta.shared::cta.b64 p, [%1], %2;\n\t"
        "selp.b32 %0, 1, 0, p;\n\t}"
        : "=r"(done) : "r"(bar), "r"(parity) : "memory");
    if (!done) {
        asm volatile(
            "{\n\t.reg .pred P1;\n\t"
            "W_%=:\n\t"
            "mbarrier.try_wait.parity.acquire.cta.shared::cta.b64 P1, [%0], %1, 0x989680;\n\t"
            "@P1 bra.uni D_%=;\n\t"
            "bra.uni W_%=;\n\t"
            "D_%=:\n\t}"
            :: "r"(bar), "r"(parity) : "memory");
    }
}
__device__ __forceinline__ void bulk_g2s(uint32_t dst_smem, const void* src_gmem,
                                         uint32_t bytes, uint32_t bar) {
    asm volatile(
        "cp.async.bulk.shared::cluster.global.mbarrier::complete_tx::bytes "
        "[%0], [%1], %2, [%3];"
        :: "r"(dst_smem), "l"(src_gmem), "r"(bytes), "r"(bar) : "memory");
}
__device__ __forceinline__ void bulk_s2g(void* dst_gmem, uint32_t src_smem,
                                         uint32_t bytes) {
    asm volatile(
        "cp.async.bulk.global.shared::cta.bulk_group [%0], [%1], %2;"
        :: "l"(dst_gmem), "r"(src_smem), "r"(bytes) : "memory");
}

__global__ __launch_bounds__(THREADS, 3) void widthap_kernel(
    const float* __restrict__ x,
    const float* __restrict__ att,
    float* __restrict__ out)
{
    extern __shared__ char smem[];
    const int tid = threadIdx.x;     // 0..191 = float4 column
    const int b   = blockIdx.y;
    const int seg = blockIdx.x;
    const int t0  = seg * SEGR;
    const int rows = (seg == NSEG - 1) ? (LENGTH - t0) : SEGR;  // 160 or 128
    const int NCH  = rows / CR;                                  // 40 or 32
    const int NIN  = NCH + 1;

    uint32_t sbase = smem_u32(smem);
    uint32_t mbar  = sbase + MBAR_OFF;

    float* wa = reinterpret_cast<float*>(smem + WA_OFF);
    if (tid < rows + 4)   // <= 164 weights
        wa[tid] = att[b * PAD + t0 + tid];

    if (tid == 0) {
        #pragma unroll
        for (int s = 0; s < IN_STAGES; s++)
            mbar_init(mbar + s * 8, 1);
    }
    __syncthreads();

    const char* xsrc = reinterpret_cast<const char*>(x) +
                       ((size_t)b * PAD + t0) * ROWB;
    char* odst = reinterpret_cast<char*>(out) +
                 ((size_t)b * LENGTH + t0) * ROWB;

    // prime input chunks 0..3
    if (tid == 0) {
        #pragma unroll
        for (int ci = 0; ci < IN_STAGES; ci++) {
            mbar_expect_tx(mbar + ci * 8, CHUNK);
            bulk_g2s(sbase + IN_OFF + ci * CHUNK,
                     xsrc + (size_t)ci * CHUNK, CHUNK, mbar + ci * 8);
        }
    }

    // Prologue: consume chunk 0 into register window (rows 0..3, weighted)
    float4 w0, w1, w2, w3;
    {
        mbar_wait(mbar + 0, 0);
        const float4* in0 = reinterpret_cast<const float4*>(smem + IN_OFF);
        float4 v;
        v = in0[0 * H4 + tid]; w0 = make_float4(v.x*wa[0], v.y*wa[0], v.z*wa[0], v.w*wa[0]);
        v = in0[1 * H4 + tid]; w1 = make_float4(v.x*wa[1], v.y*wa[1], v.z*wa[1], v.w*wa[1]);
        v = in0[2 * H4 + tid]; w2 = make_float4(v.x*wa[2], v.y*wa[2], v.z*wa[2], v.w*wa[2]);
        v = in0[3 * H4 + tid]; w3 = make_float4(v.x*wa[3], v.y*wa[3], v.z*wa[3], v.w*wa[3]);
    }

    for (int co = 0; co < NCH; co++) {
        // (a) out-stage co%2 was last used by store of chunk co-2; only that
        //     store (and older) could still be reading it. The store of co-1
        //     is not yet issued, so outstanding here is exactly {co-2}.
        if (tid == 0 && co >= 2)
            asm volatile("cp.async.bulk.wait_group.read 0;" ::: "memory");

        // (b) one barrier per chunk: prior LDS/STS retired + (a) visible
        __syncthreads();

        // (c) tid0: store prev output chunk; refill the freed input stage
        if (tid == 0) {
            if (co >= 1) {
                asm volatile("fence.proxy.async.shared::cta;" ::: "memory");
                bulk_s2g(odst + (size_t)(co - 1) * CHUNK,
                         sbase + OUT_OFF + ((co - 1) & 1) * CHUNK, CHUNK);
                asm volatile("cp.async.bulk.commit_group;" ::: "memory");
            }
            int ci = co + IN_STAGES;
            if (ci < NIN) {
                int s = ci & 3;
                mbar_expect_tx(mbar + s * 8, CHUNK);
                bulk_g2s(sbase + IN_OFF + s * CHUNK,
                         xsrc + (size_t)ci * CHUNK, CHUNK, mbar + s * 8);
            }
        }

        // (d) consume input chunk co+1 (each smem byte read exactly once)
        const int ci = co + 1;
        mbar_wait(mbar + (ci & 3) * 8, (ci >> 2) & 1);

        const float4* in = reinterpret_cast<const float4*>(
            smem + IN_OFF + (ci & 3) * CHUNK);
        const int wb = 4 * co + 4;
        float4 n0, n1, n2, n3, v;
        v = in[0 * H4 + tid]; { float a = wa[wb+0]; n0 = make_float4(v.x*a, v.y*a, v.z*a, v.w*a); }
        v = in[1 * H4 + tid]; { float a = wa[wb+1]; n1 = make_float4(v.x*a, v.y*a, v.z*a, v.w*a); }
        v = in[2 * H4 + tid]; { float a = wa[wb+2]; n2 = make_float4(v.x*a, v.y*a, v.z*a, v.w*a); }
        v = in[3 * H4 + tid]; { float a = wa[wb+3]; n3 = make_float4(v.x*a, v.y*a, v.z*a, v.w*a); }

        float4* os = reinterpret_cast<float4*>(
            smem + OUT_OFF + (co & 1) * CHUNK);
        float4 s;
        s.x = w0.x+w1.x+w2.x+w3.x+n0.x; s.y = w0.y+w1.y+w2.y+w3.y+n0.y;
        s.z = w0.z+w1.z+w2.z+w3.z+n0.z; s.w = w0.w+w1.w+w2.w+w3.w+n0.w;
        os[0 * H4 + tid] = s;
        s.x = w1.x+w2.x+w3.x+n0.x+n1.x; s.y = w1.y+w2.y+w3.y+n0.y+n1.y;
        s.z = w1.z+w2.z+w3.z+n0.z+n1.z; s.w = w1.w+w2.w+w3.w+n0.w+n1.w;
        os[1 * H4 + tid] = s;
        s.x = w2.x+w3.x+n0.x+n1.x+n2.x; s.y = w2.y+w3.y+n0.y+n1.y+n2.y;
        s.z = w2.z+w3.z+n0.z+n1.z+n2.z; s.w = w2.w+w3.w+n0.w+n1.w+n2.w;
        os[2 * H4 + tid] = s;
        s.x = w3.x+n0.x+n1.x+n2.x+n3.x; s.y = w3.y+n0.y+n1.y+n2.y+n3.y;
        s.z = w3.z+n0.z+n1.z+n2.z+n3.z; s.w = w3.w+n0.w+n1.w+n2.w+n3.w;
        os[3 * H4 + tid] = s;

        w0 = n0; w1 = n1; w2 = n2; w3 = n3;
    }

    // Epilogue: store last output chunk
    __syncthreads();
    if (tid == 0) {
        asm volatile("fence.proxy.async.shared::cta;" ::: "memory");
        bulk_s2g(odst + (size_t)(NCH - 1) * CHUNK,
                 sbase + OUT_OFF + ((NCH - 1) & 1) * CHUNK, CHUNK);
        asm volatile("cp.async.bulk.commit_group;" ::: "memory");
        asm volatile("cp.async.bulk.wait_group.read 0;" ::: "memory");
    }
}

extern "C" void kernel_launch(void* const* d_in, const int* in_sizes, int n_in,
                              void* d_out, int out_size)
{
    const float* x   = (const float*)d_in[0];   // (32,1,2052,768)
    const float* att = (const float*)d_in[1];   // (32,2052)
    float* out       = (float*)d_out;           // (32,1,2048,768)

    cudaFuncSetAttribute(widthap_kernel,
                         cudaFuncAttributeMaxDynamicSharedMemorySize, SMEM_TOTAL);

    dim3 grid(NSEG, B);   // (13, 32) = 416 CTAs, single wave at 3 CTA/SM
    dim3 block(THREADS);  // 192
    widthap_kernel<<<grid, block, SMEM_TOTAL>>>(x, att, out);
}

// round 9
// speedup vs baseline: 1.0449x; 1.0315x over previous
#include <cuda_runtime.h>
#include <cstdint>

// out[b, t, h] = sum_{j=0..4} x[b, t+j, h] * a[b, t+j]
// x: (32,1,2052,768) f32, a: (32,2052) f32, out: (32,1,2048,768) f32
//
// R9 = R5 (best wall config: bulk-DMA in/out, register sliding window,
//      TT=64, grid 1024, 2 CTA/SM, IN4/OUT3 rings, 12KB chunks)
//    + L2 evict_first cache hint on the bulk input loads, so the L2 is
//      left free to buffer dirty output lines (better writeback batching).

constexpr int LENGTH = 2048;
constexpr int H      = 768;
constexpr int PAD    = LENGTH + 4;           // 2052
constexpr int ROWB   = H * 4;                // 3072 B per row
constexpr int H4     = H / 4;                // 192
constexpr int TT     = 64;                   // output rows per CTA
constexpr int CR     = 4;                    // rows per chunk
constexpr int CHUNK  = CR * ROWB;            // 12288 B
constexpr int NCH    = TT / CR;              // 16 output chunks
constexpr int NIN    = NCH + 1;              // 17 input chunks
constexpr int IN_STAGES  = 4;
constexpr int OUT_STAGES = 3;
constexpr int B      = 32;
constexpr int THREADS = H4;                  // 192

constexpr int MBAR_OFF = 0;                              // 4 mbarriers * 8B
constexpr int WA_OFF   = 64;                             // 68 floats
constexpr int IN_OFF   = 512;
constexpr int OUT_OFF  = IN_OFF + IN_STAGES * CHUNK;     // 49664
constexpr int SMEM_TOTAL = OUT_OFF + OUT_STAGES * CHUNK; // 86528

__device__ __forceinline__ uint32_t smem_u32(const void* p) {
    return (uint32_t)__cvta_generic_to_shared(p);
}
__device__ __forceinline__ void mbar_init(uint32_t bar, uint32_t count) {
    asm volatile("mbarrier.init.shared.b64 [%0], %1;" :: "r"(bar), "r"(count) : "memory");
}
__device__ __forceinline__ void mbar_expect_tx(uint32_t bar, uint32_t bytes) {
    asm volatile("mbarrier.arrive.expect_tx.shared.b64 _, [%0], %1;"
                 :: "r"(bar), "r"(bytes) : "memory");
}
__device__ __forceinline__ void mbar_wait(uint32_t bar, uint32_t parity) {
    uint32_t done;
    asm volatile(
        "{\n\t.reg .pred p;\n\t"
        "mbarrier.try_wait.parity.acquire.cta.shared::cta.b64 p, [%1], %2;\n\t"
        "selp.b32 %0, 1, 0, p;\n\t}"
        : "=r"(done) : "r"(bar), "r"(parity) : "memory");
    if (!done) {
        asm volatile(
            "{\n\t.reg .pred P1;\n\t"
            "W_%=:\n\t"
            "mbarrier.try_wait.parity.acquire.cta.shared::cta.b64 P1, [%0], %1, 0x989680;\n\t"
            "@P1 bra.uni D_%=;\n\t"
            "bra.uni W_%=;\n\t"
            "D_%=:\n\t}"
            :: "r"(bar), "r"(parity) : "memory");
    }
}
__device__ __forceinline__ uint64_t make_evict_first_policy() {
    uint64_t pol;
    asm("createpolicy.fractional.L2::evict_first.b64 %0, 1.0;" : "=l"(pol));
    return pol;
}
__device__ __forceinline__ void bulk_g2s_ef(uint32_t dst_smem, const void* src_gmem,
                                            uint32_t bytes, uint32_t bar,
                                            uint64_t pol) {
    asm volatile(
        "cp.async.bulk.shared::cluster.global.mbarrier::complete_tx::bytes.L2::cache_hint "
        "[%0], [%1], %2, [%3], %4;"
        :: "r"(dst_smem), "l"(src_gmem), "r"(bytes), "r"(bar), "l"(pol) : "memory");
}
__device__ __forceinline__ void bulk_s2g(void* dst_gmem, uint32_t src_smem,
                                         uint32_t bytes) {
    asm volatile(
        "cp.async.bulk.global.shared::cta.bulk_group [%0], [%1], %2;"
        :: "l"(dst_gmem), "r"(src_smem), "r"(bytes) : "memory");
}

__global__ __launch_bounds__(THREADS, 2) void widthap_kernel(
    const float* __restrict__ x,
    const float* __restrict__ att,
    float* __restrict__ out)
{
    extern __shared__ char smem[];
    const int tid = threadIdx.x;     // 0..191 = float4 column
    const int b   = blockIdx.y;
    const int t0  = blockIdx.x * TT;

    uint32_t sbase = smem_u32(smem);
    uint32_t mbar  = sbase + MBAR_OFF;

    float* wa = reinterpret_cast<float*>(smem + WA_OFF);
    if (tid < TT + 4)   // 68 weights
        wa[tid] = att[b * PAD + t0 + tid];

    if (tid == 0) {
        #pragma unroll
        for (int s = 0; s < IN_STAGES; s++)
            mbar_init(mbar + s * 8, 1);
    }
    __syncthreads();

    const char* xsrc = reinterpret_cast<const char*>(x) +
                       ((size_t)b * PAD + t0) * ROWB;
    char* odst = reinterpret_cast<char*>(out) +
                 ((size_t)b * LENGTH + t0) * ROWB;

    const uint64_t pol = make_evict_first_policy();

    // prime input chunks 0..3 into stages 0..3
    if (tid == 0) {
        #pragma unroll
        for (int ci = 0; ci < IN_STAGES; ci++) {
            mbar_expect_tx(mbar + ci * 8, CHUNK);
            bulk_g2s_ef(sbase + IN_OFF + ci * CHUNK,
                        xsrc + (size_t)ci * CHUNK, CHUNK, mbar + ci * 8, pol);
        }
    }

    // Prologue: consume chunk 0 into the register window (rows 0..3, weighted)
    float4 w0, w1, w2, w3;
    {
        mbar_wait(mbar + 0, 0);
        const float4* in0 = reinterpret_cast<const float4*>(smem + IN_OFF);
        float4 v;
        v = in0[0 * H4 + tid]; w0 = make_float4(v.x*wa[0], v.y*wa[0], v.z*wa[0], v.w*wa[0]);
        v = in0[1 * H4 + tid]; w1 = make_float4(v.x*wa[1], v.y*wa[1], v.z*wa[1], v.w*wa[1]);
        v = in0[2 * H4 + tid]; w2 = make_float4(v.x*wa[2], v.y*wa[2], v.z*wa[2], v.w*wa[2]);
        v = in0[3 * H4 + tid]; w3 = make_float4(v.x*wa[3], v.y*wa[3], v.z*wa[3], v.w*wa[3]);
    }

    for (int co = 0; co < NCH; co++) {
        // (a) free the oldest out-stage before anyone STS-reuses it
        if (tid == 0 && co >= 2)
            asm volatile("cp.async.bulk.wait_group.read 1;" ::: "memory");

        // (b) one barrier: prev iter's LDS+STS done; out-stage drain visible
        __syncthreads();

        // (c) tid0: store prev output chunk; refill the input stage freed in (b)
        if (tid == 0) {
            if (co >= 1) {
                asm volatile("fence.proxy.async.shared::cta;" ::: "memory");
                bulk_s2g(odst + (size_t)(co - 1) * CHUNK,
                         sbase + OUT_OFF + ((co - 1) % OUT_STAGES) * CHUNK, CHUNK);
                asm volatile("cp.async.bulk.commit_group;" ::: "memory");
            }
            int ci = co + IN_STAGES;        // next chunk into stage co%4
            if (ci < NIN) {
                int s = ci & 3;
                mbar_expect_tx(mbar + s * 8, CHUNK);
                bulk_g2s_ef(sbase + IN_OFF + s * CHUNK,
                            xsrc + (size_t)ci * CHUNK, CHUNK, mbar + s * 8, pol);
            }
        }

        // (d) consume input chunk co+1 (single read of each smem byte)
        const int ci = co + 1;
        mbar_wait(mbar + (ci & 3) * 8, (ci >> 2) & 1);

        const float4* in = reinterpret_cast<const float4*>(
            smem + IN_OFF + (ci & 3) * CHUNK);
        const int wb = 4 * co + 4;   // weight index of first new row
        float4 n0, n1, n2, n3, v;
        v = in[0 * H4 + tid]; { float a = wa[wb+0]; n0 = make_float4(v.x*a, v.y*a, v.z*a, v.w*a); }
        v = in[1 * H4 + tid]; { float a = wa[wb+1]; n1 = make_float4(v.x*a, v.y*a, v.z*a, v.w*a); }
        v = in[2 * H4 + tid]; { float a = wa[wb+2]; n2 = make_float4(v.x*a, v.y*a, v.z*a, v.w*a); }
        v = in[3 * H4 + tid]; { float a = wa[wb+3]; n3 = make_float4(v.x*a, v.y*a, v.z*a, v.w*a); }

        float4* os = reinterpret_cast<float4*>(
            smem + OUT_OFF + (co % OUT_STAGES) * CHUNK);
        float4 s;
        s.x = w0.x+w1.x+w2.x+w3.x+n0.x; s.y = w0.y+w1.y+w2.y+w3.y+n0.y;
        s.z = w0.z+w1.z+w2.z+w3.z+n0.z; s.w = w0.w+w1.w+w2.w+w3.w+n0.w;
        os[0 * H4 + tid] = s;
        s.x = w1.x+w2.x+w3.x+n0.x+n1.x; s.y = w1.y+w2.y+w3.y+n0.y+n1.y;
        s.z = w1.z+w2.z+w3.z+n0.z+n1.z; s.w = w1.w+w2.w+w3.w+n0.w+n1.w;
        os[1 * H4 + tid] = s;
        s.x = w2.x+w3.x+n0.x+n1.x+n2.x; s.y = w2.y+w3.y+n0.y+n1.y+n2.y;
        s.z = w2.z+w3.z+n0.z+n1.z+n2.z; s.w = w2.w+w3.w+n0.w+n1.w+n2.w;
        os[2 * H4 + tid] = s;
        s.x = w3.x+n0.x+n1.x+n2.x+n3.x; s.y = w3.y+n0.y+n1.y+n2.y+n3.y;
        s.z = w3.z+n0.z+n1.z+n2.z+n3.z; s.w = w3.w+n0.w+n1.w+n2.w+n3.w;
        os[3 * H4 + tid] = s;

        w0 = n0; w1 = n1; w2 = n2; w3 = n3;
    }

    // Epilogue: store last output chunk
    __syncthreads();
    if (tid == 0) {
        asm volatile("fence.proxy.async.shared::cta;" ::: "memory");
        bulk_s2g(odst + (size_t)(NCH - 1) * CHUNK,
                 sbase + OUT_OFF + ((NCH - 1) % OUT_STAGES) * CHUNK, CHUNK);
        asm volatile("cp.async.bulk.commit_group;" ::: "memory");
        asm volatile("cp.async.bulk.wait_group.read 0;" ::: "memory");
    }
}

extern "C" void kernel_launch(void* const* d_in, const int* in_sizes, int n_in,
                              void* d_out, int out_size)
{
    const float* x   = (const float*)d_in[0];   // (32,1,2052,768)
    const float* att = (const float*)d_in[1];   // (32,2052)
    float* out       = (float*)d_out;           // (32,1,2048,768)

    cudaFuncSetAttribute(widthap_kernel,
                         cudaFuncAttributeMaxDynamicSharedMemorySize, SMEM_TOTAL);

    dim3 grid(LENGTH / TT, B);   // (32, 32) = 1024 CTAs
    dim3 block(THREADS);         // 192
    widthap_kernel<<<grid, block, SMEM_TOTAL>>>(x, att, out);
}

// round 10
// speedup vs baseline: 1.0682x; 1.0223x over previous
#include <cuda_runtime.h>
#include <cstdint>

// out[b, t, h] = sum_{j=0..4} x[b, t+j, h] * a[b, t+j]
// x: (32,1,2052,768) f32, a: (32,2052) f32, out: (32,1,2048,768) f32
//
// R10 = R5 (best wall: bulk-DMA in/out, register sliding window, TT=64,
//       grid 1024, 2 CTA/SM, 12KB chunks, OUT3 ring) with two tweaks:
//   - IN_STAGES 4 -> 5 (deeper prefetch; 98.8KB smem still fits 2 CTA/SM)
//   - split DMA duties: tid 0 (warp 0) issues input loads, tid 64 (warp 2)
//     issues output stores + drain waits. Removes tid0's serial chain.

constexpr int LENGTH = 2048;
constexpr int H      = 768;
constexpr int PAD    = LENGTH + 4;           // 2052
constexpr int ROWB   = H * 4;                // 3072 B per row
constexpr int H4     = H / 4;                // 192
constexpr int TT     = 64;                   // output rows per CTA
constexpr int CR     = 4;                    // rows per chunk
constexpr int CHUNK  = CR * ROWB;            // 12288 B
constexpr int NCH    = TT / CR;              // 16 output chunks
constexpr int NIN    = NCH + 1;              // 17 input chunks
constexpr int IN_STAGES  = 5;
constexpr int OUT_STAGES = 3;
constexpr int B      = 32;
constexpr int THREADS = H4;                  // 192

constexpr int MBAR_OFF = 0;                              // 5 mbarriers * 8B
constexpr int WA_OFF   = 64;                             // 68 floats
constexpr int IN_OFF   = 512;
constexpr int OUT_OFF  = IN_OFF + IN_STAGES * CHUNK;     // 61952
constexpr int SMEM_TOTAL = OUT_OFF + OUT_STAGES * CHUNK; // 98816

__device__ __forceinline__ uint32_t smem_u32(const void* p) {
    return (uint32_t)__cvta_generic_to_shared(p);
}
__device__ __forceinline__ void mbar_init(uint32_t bar, uint32_t count) {
    asm volatile("mbarrier.init.shared.b64 [%0], %1;" :: "r"(bar), "r"(count) : "memory");
}
__device__ __forceinline__ void mbar_expect_tx(uint32_t bar, uint32_t bytes) {
    asm volatile("mbarrier.arrive.expect_tx.shared.b64 _, [%0], %1;"
                 :: "r"(bar), "r"(bytes) : "memory");
}
__device__ __forceinline__ void mbar_wait(uint32_t bar, uint32_t parity) {
    uint32_t done;
    asm volatile(
        "{\n\t.reg .pred p;\n\t"
        "mbarrier.try_wait.parity.acquire.cta.shared::cta.b64 p, [%1], %2;\n\t"
        "selp.b32 %0, 1, 0, p;\n\t}"
        : "=r"(done) : "r"(bar), "r"(parity) : "memory");
    if (!done) {
        asm volatile(
            "{\n\t.reg .pred P1;\n\t"
            "W_%=:\n\t"
            "mbarrier.try_wait.parity.acquire.cta.shared::cta.b64 P1, [%0], %1, 0x989680;\n\t"
            "@P1 bra.uni D_%=;\n\t"
            "bra.uni W_%=;\n\t"
            "D_%=:\n\t}"
            :: "r"(bar), "r"(parity) : "memory");
    }
}
__device__ __forceinline__ void bulk_g2s(uint32_t dst_smem, const void* src_gmem,
                                         uint32_t bytes, uint32_t bar) {
    asm volatile(
        "cp.async.bulk.shared::cluster.global.mbarrier::complete_tx::bytes "
        "[%0], [%1], %2, [%3];"
        :: "r"(dst_smem), "l"(src_gmem), "r"(bytes), "r"(bar) : "memory");
}
__device__ __forceinline__ void bulk_s2g(void* dst_gmem, uint32_t src_smem,
                                         uint32_t bytes) {
    asm volatile(
        "cp.async.bulk.global.shared::cta.bulk_group [%0], [%1], %2;"
        :: "l"(dst_gmem), "r"(src_smem), "r"(bytes) : "memory");
}

__global__ __launch_bounds__(THREADS, 2) void widthap_kernel(
    const float* __restrict__ x,
    const float* __restrict__ att,
    float* __restrict__ out)
{
    extern __shared__ char smem[];
    const int tid = threadIdx.x;     // 0..191 = float4 column
    const int b   = blockIdx.y;
    const int t0  = blockIdx.x * TT;

    uint32_t sbase = smem_u32(smem);
    uint32_t mbar  = sbase + MBAR_OFF;

    float* wa = reinterpret_cast<float*>(smem + WA_OFF);
    if (tid < TT + 4)   // 68 weights
        wa[tid] = att[b * PAD + t0 + tid];

    if (tid == 0) {
        #pragma unroll
        for (int s = 0; s < IN_STAGES; s++)
            mbar_init(mbar + s * 8, 1);
    }
    __syncthreads();

    const char* xsrc = reinterpret_cast<const char*>(x) +
                       ((size_t)b * PAD + t0) * ROWB;
    char* odst = reinterpret_cast<char*>(out) +
                 ((size_t)b * LENGTH + t0) * ROWB;

    // prime input chunks 0..4 into stages 0..4 (loader warp: tid 0)
    if (tid == 0) {
        #pragma unroll
        for (int ci = 0; ci < IN_STAGES; ci++) {
            mbar_expect_tx(mbar + ci * 8, CHUNK);
            bulk_g2s(sbase + IN_OFF + ci * CHUNK,
                     xsrc + (size_t)ci * CHUNK, CHUNK, mbar + ci * 8);
        }
    }

    // Prologue: consume chunk 0 into the register window (rows 0..3, weighted)
    float4 w0, w1, w2, w3;
    {
        mbar_wait(mbar + 0, 0);
        const float4* in0 = reinterpret_cast<const float4*>(smem + IN_OFF);
        float4 v;
        v = in0[0 * H4 + tid]; w0 = make_float4(v.x*wa[0], v.y*wa[0], v.z*wa[0], v.w*wa[0]);
        v = in0[1 * H4 + tid]; w1 = make_float4(v.x*wa[1], v.y*wa[1], v.z*wa[1], v.w*wa[1]);
        v = in0[2 * H4 + tid]; w2 = make_float4(v.x*wa[2], v.y*wa[2], v.z*wa[2], v.w*wa[2]);
        v = in0[3 * H4 + tid]; w3 = make_float4(v.x*wa[3], v.y*wa[3], v.z*wa[3], v.w*wa[3]);
    }

    for (int co = 0; co < NCH; co++) {
        // (a) storer warp: free the oldest out-stage before STS reuse.
        //     (bulk_group state is per-thread; tid 64 issues ALL stores.)
        if (tid == 64 && co >= 2)
            asm volatile("cp.async.bulk.wait_group.read 1;" ::: "memory");

        // (b) one barrier: prev iter's LDS+STS done; out-stage drain visible
        __syncthreads();

        // (c1) storer warp (tid 64): store prev output chunk
        if (tid == 64 && co >= 1) {
            asm volatile("fence.proxy.async.shared::cta;" ::: "memory");
            bulk_s2g(odst + (size_t)(co - 1) * CHUNK,
                     sbase + OUT_OFF + ((co - 1) % OUT_STAGES) * CHUNK, CHUNK);
            asm volatile("cp.async.bulk.commit_group;" ::: "memory");
        }
        // (c2) loader warp (tid 0): refill the input stage freed in (b)
        if (tid == 0) {
            int ci = co + IN_STAGES;
            if (ci < NIN) {
                int s = ci % IN_STAGES;
                mbar_expect_tx(mbar + s * 8, CHUNK);
                bulk_g2s(sbase + IN_OFF + s * CHUNK,
                         xsrc + (size_t)ci * CHUNK, CHUNK, mbar + s * 8);
            }
        }

        // (d) consume input chunk co+1 (single read of each smem byte)
        const int ci = co + 1;
        mbar_wait(mbar + (ci % IN_STAGES) * 8, (ci / IN_STAGES) & 1);

        const float4* in = reinterpret_cast<const float4*>(
            smem + IN_OFF + (ci % IN_STAGES) * CHUNK);
        const int wb = 4 * co + 4;   // weight index of first new row
        float4 n0, n1, n2, n3, v;
        v = in[0 * H4 + tid]; { float a = wa[wb+0]; n0 = make_float4(v.x*a, v.y*a, v.z*a, v.w*a); }
        v = in[1 * H4 + tid]; { float a = wa[wb+1]; n1 = make_float4(v.x*a, v.y*a, v.z*a, v.w*a); }
        v = in[2 * H4 + tid]; { float a = wa[wb+2]; n2 = make_float4(v.x*a, v.y*a, v.z*a, v.w*a); }
        v = in[3 * H4 + tid]; { float a = wa[wb+3]; n3 = make_float4(v.x*a, v.y*a, v.z*a, v.w*a); }

        float4* os = reinterpret_cast<float4*>(
            smem + OUT_OFF + (co % OUT_STAGES) * CHUNK);
        float4 s;
        s.x = w0.x+w1.x+w2.x+w3.x+n0.x; s.y = w0.y+w1.y+w2.y+w3.y+n0.y;
        s.z = w0.z+w1.z+w2.z+w3.z+n0.z; s.w = w0.w+w1.w+w2.w+w3.w+n0.w;
        os[0 * H4 + tid] = s;
        s.x = w1.x+w2.x+w3.x+n0.x+n1.x; s.y = w1.y+w2.y+w3.y+n0.y+n1.y;
        s.z = w1.z+w2.z+w3.z+n0.z+n1.z; s.w = w1.w+w2.w+w3.w+n0.w+n1.w;
        os[1 * H4 + tid] = s;
        s.x = w2.x+w3.x+n0.x+n1.x+n2.x; s.y = w2.y+w3.y+n0.y+n1.y+n2.y;
        s.z = w2.z+w3.z+n0.z+n1.z+n2.z; s.w = w2.w+w3.w+n0.w+n1.w+n2.w;
        os[2 * H4 + tid] = s;
        s.x = w3.x+n0.x+n1.x+n2.x+n3.x; s.y = w3.y+n0.y+n1.y+n2.y+n3.y;
        s.z = w3.z+n0.z+n1.z+n2.z+n3.z; s.w = w3.w+n0.w+n1.w+n2.w+n3.w;
        os[3 * H4 + tid] = s;

        w0 = n0; w1 = n1; w2 = n2; w3 = n3;
    }

    // Epilogue: store last output chunk (storer warp)
    __syncthreads();
    if (tid == 64) {
        asm volatile("fence.proxy.async.shared::cta;" ::: "memory");
        bulk_s2g(odst + (size_t)(NCH - 1) * CHUNK,
                 sbase + OUT_OFF + ((NCH - 1) % OUT_STAGES) * CHUNK, CHUNK);
        asm volatile("cp.async.bulk.commit_group;" ::: "memory");
        asm volatile("cp.async.bulk.wait_group.read 0;" ::: "memory");
    }
}

extern "C" void kernel_launch(void* const* d_in, const int* in_sizes, int n_in,
                              void* d_out, int out_size)
{
    const float* x   = (const float*)d_in[0];   // (32,1,2052,768)
    const float* att = (const float*)d_in[1];   // (32,2052)
    float* out       = (float*)d_out;           // (32,1,2048,768)

    cudaFuncSetAttribute(widthap_kernel,
                         cudaFuncAttributeMaxDynamicSharedMemorySize, SMEM_TOTAL);

    dim3 grid(LENGTH / TT, B);   // (32, 32) = 1024 CTAs
    dim3 block(THREADS);         // 192
    widthap_kernel<<<grid, block, SMEM_TOTAL>>>(x, att, out);
}